// round 15
// baseline (speedup 1.0000x reference)
#include <cuda_runtime.h>
#include <cuda_fp16.h>
#include <math.h>
#include <stdint.h>

// Problem constants
#define BATCH   64
#define HDIM    28
#define WDIM    28
#define C_      512
#define HEADS_  16
#define WS_     7
#define SHIFT_  3
#define MLPD    2048
#define HD_     32
#define W2_     49
#define NW_     16
#define HW_     784
#define MTOK    50176   // BATCH*HW
#define NWIN    1024    // BATCH*NW
#define C3      1536    // 3*C_ fused qkv width

// Scratch (device globals: no allocation allowed in kernel_launch)
__device__ __half g_win[MTOK * C_];
__device__ __half g_qkv[(size_t)MTOK * MLPD];  // fused qkv [MTOK][1536]; also mid
__device__ __half g_ctx[MTOK * C_];
__device__ __half g_h2[MTOK * C_];
__device__ float  g_x1[MTOK * C_];
__device__ float  g_bcat[C3];
// Transposed (K-major, [N][K]) fp16 weights: qkvT | woT | wiT | woutT
#define WT_QKV 0
#define WT_O   (C3 * C_)
#define WT_I   (WT_O + C_ * C_)
#define WT_OUT (WT_I + MLPD * C_)
__device__ __half g_wT[WT_OUT + C_ * MLPD];

// Map window-partition row m -> token row in the unshifted [B,H*W] layout.
__device__ __forceinline__ int map_row(int m) {
    int bb  = m / HW_;
    int rem = m - bb * HW_;
    int w   = rem / W2_;
    int t   = rem - w * W2_;
    int wh = w >> 2, ww = w & 3;
    int th = t / WS_, tw = t - th * WS_;
    int r = wh * WS_ + th + SHIFT_; if (r >= HDIM) r -= HDIM;
    int c = ww * WS_ + tw + SHIFT_; if (c >= WDIM) c -= WDIM;
    return bb * HW_ + r * WDIM + c;
}

// Tiled transpose + fp32->fp16: out[Cc][R] = half(in[R][Cc]^T).
__global__ __launch_bounds__(256) void transpose_kernel(
    const float* __restrict__ in, __half* __restrict__ out, int R, int Cc)
{
    __shared__ float t[32][33];
    int bx = blockIdx.x * 32, by = blockIdx.y * 32;
    int tx = threadIdx.x & 31, ty = threadIdx.x >> 5;
    #pragma unroll
    for (int j = 0; j < 32; j += 8)
        t[ty + j][tx] = in[(size_t)(by + ty + j) * Cc + bx + tx];
    __syncthreads();
    #pragma unroll
    for (int j = 0; j < 32; j += 8)
        out[(size_t)(bx + ty + j) * R + by + tx] = __float2half(t[tx][ty + j]);
}

// Concat qkv biases (fp32)
__global__ __launch_bounds__(256) void bcat_kernel(
    const float* __restrict__ bq, const float* __restrict__ bk,
    const float* __restrict__ bv, float* __restrict__ bcat)
{
    int idx = blockIdx.x * 256 + threadIdx.x;
    if (idx < C_) {
        bcat[idx        ] = bq[idx];
        bcat[idx + C_   ] = bk[idx];
        bcat[idx + 2*C_ ] = bv[idx];
    }
}

// LayerNorm over C=512, one block per token row; fp32 in, fp16 out.
__global__ __launch_bounds__(128) void ln_kernel(
    const float* __restrict__ in, const float* __restrict__ g,
    const float* __restrict__ b, __half* __restrict__ out, int gather)
{
    int m = blockIdx.x;
    int src = gather ? map_row(m) : m;
    int tid = threadIdx.x;

    float4 xv = ((const float4*)(in + (size_t)src * C_))[tid];
    float s  = xv.x + xv.y + xv.z + xv.w;
    float s2 = xv.x*xv.x + xv.y*xv.y + xv.z*xv.z + xv.w*xv.w;
    #pragma unroll
    for (int off = 16; off; off >>= 1) {
        s  += __shfl_xor_sync(0xffffffffu, s,  off);
        s2 += __shfl_xor_sync(0xffffffffu, s2, off);
    }
    __shared__ float red[8];
    int wid = tid >> 5;
    if ((tid & 31) == 0) { red[wid] = s; red[4 + wid] = s2; }
    __syncthreads();
    s  = red[0] + red[1] + red[2] + red[3];
    s2 = red[4] + red[5] + red[6] + red[7];
    float mu   = s * (1.0f / C_);
    float var  = fmaf(-mu, mu, s2 * (1.0f / C_));
    float rstd = rsqrtf(var + 1e-5f);

    float4 gv = ((const float4*)g)[tid];
    float4 bv = ((const float4*)b)[tid];
    __half2 o01 = __floats2half2_rn((xv.x - mu) * rstd * gv.x + bv.x,
                                    (xv.y - mu) * rstd * gv.y + bv.y);
    __half2 o23 = __floats2half2_rn((xv.z - mu) * rstd * gv.z + bv.z,
                                    (xv.w - mu) * rstd * gv.w + bv.w);
    __half2* op = (__half2*)(out + (size_t)m * C_ + tid * 4);
    op[0] = o01;
    op[1] = o23;
}

// ---------------------------------------------------------------------------
// FP16 tensor-core GEMM (mma.m16n8k16, fp32 accum).
// CTA tile 128x128, 8 warps (2 x 4), warp tile 64x32. 3-stage cp.async ring
// with K=64 halves per stage (sync every 4 k16-steps).
// C[M,N] = A[M,K] @ Bt[N,K]^T + bias (fp32 epilogue math).
// Smem rows: 144 B = 128 B data (64 halves) + 16 B pad (conflict-free: row
// stride 36 floats == 4 mod 32 -> 8-row LDSM phases cover distinct banks).
// mode 0: plain  1: exact GELU  2: += res[m]  3: scatter map_row(m), += res
// half_out: 1 -> store __half, 0 -> store float.
// ---------------------------------------------------------------------------
#define BM 128
#define BN 128
#define BKH 64                   // K halves per stage
#define ROWB 144                 // bytes per smem row
#define A_BYTES (BM * ROWB)      // 18432
#define NSTAGE 3
#define STAGE_BYTES (2 * A_BYTES)           // 36864
#define SMEM_GEMM (NSTAGE * STAGE_BYTES)    // 110592

__device__ __forceinline__ void cpa16(uint32_t smem_dst, const void* gsrc) {
    asm volatile("cp.async.cg.shared.global [%0], [%1], 16;\n"
                 :: "r"(smem_dst), "l"(gsrc));
}

__device__ __forceinline__ void mma_f16(float c[4], uint32_t a0, uint32_t a1,
                                        uint32_t a2, uint32_t a3,
                                        uint32_t b0, uint32_t b1) {
    asm volatile(
        "mma.sync.aligned.m16n8k16.row.col.f32.f16.f16.f32 "
        "{%0,%1,%2,%3}, {%4,%5,%6,%7}, {%8,%9}, {%0,%1,%2,%3};"
        : "+f"(c[0]), "+f"(c[1]), "+f"(c[2]), "+f"(c[3])
        : "r"(a0), "r"(a1), "r"(a2), "r"(a3), "r"(b0), "r"(b1));
}

__device__ __forceinline__ void ldsm4(uint32_t* a, uint32_t addr) {
    asm volatile("ldmatrix.sync.aligned.m8n8.x4.shared.b16 {%0,%1,%2,%3}, [%4];"
                 : "=r"(a[0]), "=r"(a[1]), "=r"(a[2]), "=r"(a[3]) : "r"(addr));
}

__global__ __launch_bounds__(256) void tgemm_kernel(
    const __half* __restrict__ A, const __half* __restrict__ Bt,
    const float* __restrict__ bias, void* __restrict__ Cout,
    int M, int N, int K, int mode, const float* __restrict__ res, int half_out)
{
    extern __shared__ char sm[];

    const int cRow = blockIdx.y, cCol = blockIdx.x;
    const int tid  = threadIdx.x;
    const int wid  = tid >> 5;
    const int lane = tid & 31;
    const int wm   = wid >> 2;       // 0..1  -> 64 M-rows
    const int wn   = wid & 3;        // 0..3  -> 32 N-cols
    const int grp  = lane >> 2;      // 0..7
    const int tig  = lane & 3;       // 0..3

    // ldmatrix lane address components (A: m16xk16 x4; B: n16xk16 x4)
    const int lrowA = (lane & 7) + ((lane >> 3) & 1) * 8;
    const int lcbA  = (lane >> 4) * 16;           // k-half byte offset 0/16
    const int lrowB = (lane & 7) + (lane >> 4) * 8;
    const int lcbB  = ((lane >> 3) & 1) * 16;

    const __half* Ab = A  + (size_t)cRow * BM * K;
    const __half* Bb = Bt + (size_t)cCol * BN * K;

    uint32_t smem_base = (uint32_t)__cvta_generic_to_shared(sm);
    const uint32_t aofs = (uint32_t)((wm * 64 + lrowA) * ROWB + lcbA);
    const uint32_t bofs = (uint32_t)A_BYTES +
                          (uint32_t)((wn * 32 + lrowB) * ROWB + lcbB);

    float c[4][4][4] = {};

    // Per stage: A 128 rows x 8 chunks = 1024 (4/thread); B same.
    auto load_tile = [&](int t, int s) {
        const int k0 = t * BKH;
        uint32_t abase = smem_base + (uint32_t)(s * STAGE_BYTES);
        uint32_t bbase = abase + A_BYTES;
        #pragma unroll
        for (int cc = 0; cc < 4; cc++) {
            int id = tid * 4 + cc;
            int r = id >> 3, kc = id & 7;   // kc: 16B chunk = 8 halves
            cpa16(abase + (uint32_t)(r * ROWB + kc * 16),
                  Ab + (size_t)r * K + k0 + kc * 8);
            cpa16(bbase + (uint32_t)(r * ROWB + kc * 16),
                  Bb + (size_t)r * K + k0 + kc * 8);
        }
    };

    const int T = K / BKH;
    #pragma unroll
    for (int s = 0; s < NSTAGE - 1; s++) {
        load_tile(s, s);
        asm volatile("cp.async.commit_group;");
    }

    int ci = 0;
    int pi = NSTAGE - 1;
    for (int i = 0; i < T; i++) {
        asm volatile("cp.async.wait_group %0;" :: "n"(NSTAGE - 2));
        __syncthreads();

        if (i + NSTAGE - 1 < T) load_tile(i + NSTAGE - 1, pi);
        asm volatile("cp.async.commit_group;");

        const uint32_t stage = smem_base + (uint32_t)(ci * STAGE_BYTES);
        const uint32_t aStage = stage + aofs;
        const uint32_t bStage = stage + bofs;

        #pragma unroll
        for (int ks = 0; ks < 4; ks++) {          // four k16 steps per stage
            uint32_t a[4][4], b[4][2];
            #pragma unroll
            for (int mi = 0; mi < 4; mi++)
                ldsm4(a[mi], aStage + (uint32_t)(mi * 16 * ROWB + ks * 32));
            #pragma unroll
            for (int p = 0; p < 2; p++) {
                uint32_t t4[4];
                ldsm4(t4, bStage + (uint32_t)(p * 16 * ROWB + ks * 32));
                b[p*2    ][0] = t4[0];
                b[p*2    ][1] = t4[1];
                b[p*2 + 1][0] = t4[2];
                b[p*2 + 1][1] = t4[3];
            }
            #pragma unroll
            for (int mi = 0; mi < 4; mi++)
                #pragma unroll
                for (int ni = 0; ni < 4; ni++)
                    mma_f16(c[mi][ni], a[mi][0], a[mi][1], a[mi][2], a[mi][3],
                            b[ni][0], b[ni][1]);
        }
        ci = (ci + 1 == NSTAGE) ? 0 : ci + 1;
        pi = (pi + 1 == NSTAGE) ? 0 : pi + 1;
    }

    // epilogue (fp32 math)
    #pragma unroll
    for (int mi = 0; mi < 4; mi++) {
        #pragma unroll
        for (int rr = 0; rr < 2; rr++) {
            int m = cRow * BM + wm * 64 + mi * 16 + grp + rr * 8;
            int outm = (mode == 3) ? map_row(m) : m;
            #pragma unroll
            for (int ni = 0; ni < 4; ni++) {
                int n = cCol * BN + wn * 32 + ni * 8 + tig * 2;
                float v0 = c[mi][ni][rr * 2 + 0] + bias[n];
                float v1 = c[mi][ni][rr * 2 + 1] + bias[n + 1];
                if (mode == 1) {
                    v0 = 0.5f * v0 * (1.0f + erff(v0 * 0.70710678118654752f));
                    v1 = 0.5f * v1 * (1.0f + erff(v1 * 0.70710678118654752f));
                } else if (mode == 2) {
                    v0 += res[(size_t)m * N + n];
                    v1 += res[(size_t)m * N + n + 1];
                } else if (mode == 3) {
                    v0 += res[(size_t)outm * N + n];
                    v1 += res[(size_t)outm * N + n + 1];
                }
                if (half_out) {
                    *(__half2*)((__half*)Cout + (size_t)outm * N + n) =
                        __floats2half2_rn(v0, v1);
                } else {
                    float* Cp = (float*)Cout + (size_t)outm * N + n;
                    Cp[0] = v0;
                    Cp[1] = v1;
                }
            }
        }
    }
}

// ---------------------------------------------------------------------------
// Windowed attention on tensor cores (mma.m16n8k8.tf32), fp16 I/O.
// One block (128 thr = 4 warps) per (window, head).
// ---------------------------------------------------------------------------
#define QK_STR 36
#define SC_STR 60

__device__ __forceinline__ void mma_tf32(float c[4], uint32_t a0, uint32_t a1,
                                         uint32_t a2, uint32_t a3,
                                         uint32_t b0, uint32_t b1) {
    asm volatile(
        "mma.sync.aligned.m16n8k8.row.col.f32.tf32.tf32.f32 "
        "{%0,%1,%2,%3}, {%4,%5,%6,%7}, {%8,%9}, {%0,%1,%2,%3};"
        : "+f"(c[0]), "+f"(c[1]), "+f"(c[2]), "+f"(c[3])
        : "r"(a0), "r"(a1), "r"(a2), "r"(a3), "r"(b0), "r"(b1));
}

__global__ __launch_bounds__(128) void attn_kernel(
    const __half* __restrict__ qkv, const float* __restrict__ rel_table,
    const int* __restrict__ rel_index, __half* __restrict__ ctx)
{
    __shared__ float qs[64 * QK_STR];
    __shared__ float karr[64 * QK_STR];
    __shared__ float vsT[32 * SC_STR];
    __shared__ float sc[64 * SC_STR];
    __shared__ int   grp[W2_];

    int blk  = blockIdx.x;
    int head = blk & (HEADS_ - 1);
    int win  = blk >> 4;
    int w    = win & (NW_ - 1);
    int tid  = threadIdx.x;
    int wid  = tid >> 5;
    int lane = tid & 31;

    {
        float4 z = make_float4(0.f, 0.f, 0.f, 0.f);
        for (int i = tid; i < (64 * QK_STR) / 4; i += 128) {
            ((float4*)qs)[i] = z;
            ((float4*)karr)[i] = z;
        }
        for (int i = tid; i < (32 * SC_STR) / 4; i += 128) ((float4*)vsT)[i] = z;
        for (int i = tid; i < (64 * SC_STR) / 4; i += 128) ((float4*)sc)[i] = z;
    }
    __syncthreads();

    const size_t qbase = (size_t)win * W2_ * C3 + head * HD_;
    for (int idx = tid; idx < W2_ * 4; idx += 128) {
        int t = idx >> 2, dc = idx & 3;          // dc: 8-half chunk
        const __half2* p = (const __half2*)(qkv + qbase + (size_t)t * C3 + dc * 8);
        #pragma unroll
        for (int u = 0; u < 4; u++) {
            float2 qv = __half22float2(p[u]);
            float2 kv = __half22float2(p[u + C_ / 2]);
            float2 vv = __half22float2(p[u + C_]);
            int d0 = dc * 8 + u * 2;
            qs[t * QK_STR + d0]       = qv.x;
            qs[t * QK_STR + d0 + 1]   = qv.y;
            karr[t * QK_STR + d0]     = kv.x;
            karr[t * QK_STR + d0 + 1] = kv.y;
            vsT[(d0    ) * SC_STR + t] = vv.x;
            vsT[(d0 + 1) * SC_STR + t] = vv.y;
        }
    }
    if (tid < W2_) {
        int wh = w >> 2, ww = w & 3;
        int r = wh * WS_ + tid / WS_;
        int c = ww * WS_ + tid % WS_;
        int br = (r < HDIM - WS_) ? 0 : ((r < HDIM - SHIFT_) ? 1 : 2);
        int bc = (c < WDIM - WS_) ? 0 : ((c < WDIM - SHIFT_) ? 1 : 2);
        grp[tid] = br * 3 + bc;
    }
    __syncthreads();

    const float scale = 0.17677669529663687f; // 1/sqrt(32)
    const int m0 = wid * 16;
    const int lrowA = (lane & 7) + ((lane >> 3) & 1) * 8;
    const int lcolA = (lane >> 4) * 4;
    const int lrowB = (lane & 7) + (lane >> 4) * 8;
    const int lcolB = ((lane >> 3) & 1) * 4;
    const int rgrp  = lane >> 2;
    const int tig   = lane & 3;

    // ---- Scores ----
    {
        uint32_t qb = (uint32_t)__cvta_generic_to_shared(qs) +
                      (uint32_t)(((m0 + lrowA) * QK_STR + lcolA) * 4);
        uint32_t kb = (uint32_t)__cvta_generic_to_shared(karr) +
                      (uint32_t)((lrowB * QK_STR + lcolB) * 4);

        float c[7][4] = {};
        #pragma unroll
        for (int ksp = 0; ksp < 4; ksp++) {
            uint32_t a[4];
            ldsm4(a, qb + ksp * 32);
            uint32_t b[8][2];
            #pragma unroll
            for (int p = 0; p < 4; p++) {
                uint32_t t4[4];
                ldsm4(t4, kb + (uint32_t)(p * 16 * QK_STR * 4) + ksp * 32);
                b[p*2    ][0] = t4[0]; b[p*2    ][1] = t4[1];
                b[p*2 + 1][0] = t4[2]; b[p*2 + 1][1] = t4[3];
            }
            #pragma unroll
            for (int ni = 0; ni < 7; ni++)
                mma_tf32(c[ni], a[0], a[1], a[2], a[3], b[ni][0], b[ni][1]);
        }

        #pragma unroll
        for (int ni = 0; ni < 7; ni++) {
            #pragma unroll
            for (int h = 0; h < 2; h++) {
                int i = m0 + rgrp + h * 8;
                if (i < W2_) {
                    #pragma unroll
                    for (int e = 0; e < 2; e++) {
                        int j = ni * 8 + tig * 2 + e;
                        if (j < W2_) {
                            float bias = rel_table[rel_index[i * W2_ + j] * HEADS_ + head];
                            float mask = (grp[i] != grp[j]) ? -100.0f : 0.0f;
                            sc[i * SC_STR + j] = c[ni][h * 2 + e] * scale + bias + mask;
                        }
                    }
                }
            }
        }
    }
    __syncthreads();

    // ---- Softmax ----
    if (tid < W2_) {
        float mx = -1e30f;
        #pragma unroll 7
        for (int j = 0; j < W2_; j++) mx = fmaxf(mx, sc[tid * SC_STR + j]);
        float sum = 0.0f;
        #pragma unroll 7
        for (int j = 0; j < W2_; j++) {
            float e = __expf(sc[tid * SC_STR + j] - mx);
            sc[tid * SC_STR + j] = e;
            sum += e;
        }
        float inv = 1.0f / sum;
        #pragma unroll 7
        for (int j = 0; j < W2_; j++) sc[tid * SC_STR + j] *= inv;
    }
    __syncthreads();

    // ---- PV ----
    {
        uint32_t pb = (uint32_t)__cvta_generic_to_shared(sc) +
                      (uint32_t)(((m0 + lrowA) * SC_STR + lcolA) * 4);
        uint32_t vb = (uint32_t)__cvta_generic_to_shared(vsT) +
                      (uint32_t)((lrowB * SC_STR + lcolB) * 4);

        float o[4][4] = {};
        #pragma unroll
        for (int kj = 0; kj < 7; kj++) {
            uint32_t a[4];
            ldsm4(a, pb + kj * 32);
            uint32_t b[4][2];
            #pragma unroll
            for (int p = 0; p < 2; p++) {
                uint32_t t4[4];
                ldsm4(t4, vb + (uint32_t)(p * 16 * SC_STR * 4) + kj * 32);
                b[p*2    ][0] = t4[0]; b[p*2    ][1] = t4[1];
                b[p*2 + 1][0] = t4[2]; b[p*2 + 1][1] = t4[3];
            }
            #pragma unroll
            for (int ni = 0; ni < 4; ni++)
                mma_tf32(o[ni], a[0], a[1], a[2], a[3], b[ni][0], b[ni][1]);
        }

        const size_t obase = (size_t)win * W2_ * C_ + head * HD_;
        #pragma unroll
        for (int ni = 0; ni < 4; ni++) {
            #pragma unroll
            for (int h = 0; h < 2; h++) {
                int i = m0 + rgrp + h * 8;
                if (i < W2_) {
                    int d = ni * 8 + tig * 2;
                    *(__half2*)&ctx[obase + (size_t)i * C_ + d] =
                        __floats2half2_rn(o[ni][h * 2], o[ni][h * 2 + 1]);
                }
            }
        }
    }
}

extern "C" void kernel_launch(void* const* d_in, const int* in_sizes, int n_in,
                              void* d_out, int out_size)
{
    const float* x         = (const float*)d_in[0];
    const float* g1        = (const float*)d_in[1];
    const float* b1        = (const float*)d_in[2];
    const float* wq        = (const float*)d_in[3];
    const float* bq        = (const float*)d_in[4];
    const float* wk        = (const float*)d_in[5];
    const float* bk        = (const float*)d_in[6];
    const float* wv        = (const float*)d_in[7];
    const float* bv        = (const float*)d_in[8];
    const float* rel_table = (const float*)d_in[9];
    const float* wo        = (const float*)d_in[10];
    const float* bo        = (const float*)d_in[11];
    const float* g2        = (const float*)d_in[12];
    const float* b2        = (const float*)d_in[13];
    const float* wi        = (const float*)d_in[14];
    const float* bi        = (const float*)d_in[15];
    const float* w_out     = (const float*)d_in[16];
    const float* b_out     = (const float*)d_in[17];
    const int*   rel_index = (const int*)d_in[18];
    float* out = (float*)d_out;

    __half *p_win, *p_qkv, *p_ctx, *p_h2, *p_wT;
    float  *p_x1, *p_bcat;
    cudaGetSymbolAddress((void**)&p_win,  g_win);
    cudaGetSymbolAddress((void**)&p_qkv,  g_qkv);
    cudaGetSymbolAddress((void**)&p_ctx,  g_ctx);
    cudaGetSymbolAddress((void**)&p_h2,   g_h2);
    cudaGetSymbolAddress((void**)&p_x1,   g_x1);
    cudaGetSymbolAddress((void**)&p_bcat, g_bcat);
    cudaGetSymbolAddress((void**)&p_wT,   g_wT);

    cudaFuncSetAttribute(tgemm_kernel,
                         cudaFuncAttributeMaxDynamicSharedMemorySize, SMEM_GEMM);

    // 0. weight transposes -> fp16 [N][K] K-major (qkvT = wqT|wkT|wvT stacked)
    transpose_kernel<<<dim3(16, 16), 256>>>(wq,    p_wT + WT_QKV,           C_,   C_);
    transpose_kernel<<<dim3(16, 16), 256>>>(wk,    p_wT + WT_QKV + C_*C_,   C_,   C_);
    transpose_kernel<<<dim3(16, 16), 256>>>(wv,    p_wT + WT_QKV + 2*C_*C_, C_,   C_);
    transpose_kernel<<<dim3(16, 16), 256>>>(wo,    p_wT + WT_O,             C_,   C_);
    transpose_kernel<<<dim3(64, 16), 256>>>(wi,    p_wT + WT_I,             C_,   MLPD);
    transpose_kernel<<<dim3(16, 64), 256>>>(w_out, p_wT + WT_OUT,           MLPD, C_);
    bcat_kernel<<<(C_ + 255) / 256, 256>>>(bq, bk, bv, p_bcat);

    // 1. LN1 + cyclic shift + window partition (gather) -> fp16
    ln_kernel<<<MTOK, 128>>>(x, g1, b1, p_win, 1);

    // 2. fused QKV projection -> fp16 qkv [MTOK][1536]
    dim3 gQKV(C3 / BN, MTOK / BM);
    tgemm_kernel<<<gQKV, 256, SMEM_GEMM>>>(p_win, p_wT + WT_QKV, p_bcat, p_qkv,
                                           MTOK, C3, C_, 0, nullptr, 1);

    // 3. windowed attention (tensor-core scores + softmax + PV) -> fp16 ctx
    attn_kernel<<<NWIN * HEADS_, 128>>>(p_qkv, rel_table, rel_index, p_ctx);

    // 4. output projection + window reverse + un-shift scatter + residual(x) -> fp32 x1
    dim3 gC(C_ / BN, MTOK / BM);
    tgemm_kernel<<<gC, 256, SMEM_GEMM>>>(p_ctx, p_wT + WT_O, bo, p_x1,
                                         MTOK, C_, C_, 3, x, 0);

    // 5. LN2 -> fp16
    ln_kernel<<<MTOK, 128>>>(p_x1, g2, b2, p_h2, 0);

    // 6. MLP up-projection + exact GELU -> fp16 mid (reuses qkv buffer)
    dim3 gM(MLPD / BN, MTOK / BM);
    tgemm_kernel<<<gM, 256, SMEM_GEMM>>>(p_h2, p_wT + WT_I, bi, p_qkv,
                                         MTOK, MLPD, C_, 1, nullptr, 1);

    // 7. MLP down-projection + residual(x1) -> fp32 final output
    tgemm_kernel<<<gC, 256, SMEM_GEMM>>>(p_qkv, p_wT + WT_OUT, b_out, out,
                                         MTOK, C_, MLPD, 2, p_x1, 0);
}

// round 16
// speedup vs baseline: 1.0963x; 1.0963x over previous
#include <cuda_runtime.h>
#include <cuda_fp16.h>
#include <math.h>
#include <stdint.h>

// Problem constants
#define BATCH   64
#define HDIM    28
#define WDIM    28
#define C_      512
#define HEADS_  16
#define WS_     7
#define SHIFT_  3
#define MLPD    2048
#define HD_     32
#define W2_     49
#define NW_     16
#define HW_     784
#define MTOK    50176   // BATCH*HW
#define NWIN    1024    // BATCH*NW
#define C3      1536    // 3*C_ fused qkv width

// Scratch (device globals: no allocation allowed in kernel_launch)
__device__ __half g_win[MTOK * C_];
__device__ __half g_qkv[(size_t)MTOK * MLPD];  // fused qkv [MTOK][1536]; also mid
__device__ __half g_ctx[MTOK * C_];
__device__ __half g_h2[MTOK * C_];
__device__ float  g_x1[MTOK * C_];
__device__ float  g_bcat[C3];
// Transposed (K-major, [N][K]) fp16 weights: qkvT | woT | wiT | woutT
#define WT_QKV 0
#define WT_O   (C3 * C_)
#define WT_I   (WT_O + C_ * C_)
#define WT_OUT (WT_I + MLPD * C_)
__device__ __half g_wT[WT_OUT + C_ * MLPD];

// Map window-partition row m -> token row in the unshifted [B,H*W] layout.
__device__ __forceinline__ int map_row(int m) {
    int bb  = m / HW_;
    int rem = m - bb * HW_;
    int w   = rem / W2_;
    int t   = rem - w * W2_;
    int wh = w >> 2, ww = w & 3;
    int th = t / WS_, tw = t - th * WS_;
    int r = wh * WS_ + th + SHIFT_; if (r >= HDIM) r -= HDIM;
    int c = ww * WS_ + tw + SHIFT_; if (c >= WDIM) c -= WDIM;
    return bb * HW_ + r * WDIM + c;
}

// Tiled transpose + fp32->fp16: out[Cc][R] = half(in[R][Cc]^T).
__global__ __launch_bounds__(256) void transpose_kernel(
    const float* __restrict__ in, __half* __restrict__ out, int R, int Cc)
{
    __shared__ float t[32][33];
    int bx = blockIdx.x * 32, by = blockIdx.y * 32;
    int tx = threadIdx.x & 31, ty = threadIdx.x >> 5;
    #pragma unroll
    for (int j = 0; j < 32; j += 8)
        t[ty + j][tx] = in[(size_t)(by + ty + j) * Cc + bx + tx];
    __syncthreads();
    #pragma unroll
    for (int j = 0; j < 32; j += 8)
        out[(size_t)(bx + ty + j) * R + by + tx] = __float2half(t[tx][ty + j]);
}

// Concat qkv biases (fp32)
__global__ __launch_bounds__(256) void bcat_kernel(
    const float* __restrict__ bq, const float* __restrict__ bk,
    const float* __restrict__ bv, float* __restrict__ bcat)
{
    int idx = blockIdx.x * 256 + threadIdx.x;
    if (idx < C_) {
        bcat[idx        ] = bq[idx];
        bcat[idx + C_   ] = bk[idx];
        bcat[idx + 2*C_ ] = bv[idx];
    }
}

// LayerNorm over C=512, one block per token row; fp32 in, fp16 out.
__global__ __launch_bounds__(128) void ln_kernel(
    const float* __restrict__ in, const float* __restrict__ g,
    const float* __restrict__ b, __half* __restrict__ out, int gather)
{
    int m = blockIdx.x;
    int src = gather ? map_row(m) : m;
    int tid = threadIdx.x;

    float4 xv = ((const float4*)(in + (size_t)src * C_))[tid];
    float s  = xv.x + xv.y + xv.z + xv.w;
    float s2 = xv.x*xv.x + xv.y*xv.y + xv.z*xv.z + xv.w*xv.w;
    #pragma unroll
    for (int off = 16; off; off >>= 1) {
        s  += __shfl_xor_sync(0xffffffffu, s,  off);
        s2 += __shfl_xor_sync(0xffffffffu, s2, off);
    }
    __shared__ float red[8];
    int wid = tid >> 5;
    if ((tid & 31) == 0) { red[wid] = s; red[4 + wid] = s2; }
    __syncthreads();
    s  = red[0] + red[1] + red[2] + red[3];
    s2 = red[4] + red[5] + red[6] + red[7];
    float mu   = s * (1.0f / C_);
    float var  = fmaf(-mu, mu, s2 * (1.0f / C_));
    float rstd = rsqrtf(var + 1e-5f);

    float4 gv = ((const float4*)g)[tid];
    float4 bv = ((const float4*)b)[tid];
    __half2 o01 = __floats2half2_rn((xv.x - mu) * rstd * gv.x + bv.x,
                                    (xv.y - mu) * rstd * gv.y + bv.y);
    __half2 o23 = __floats2half2_rn((xv.z - mu) * rstd * gv.z + bv.z,
                                    (xv.w - mu) * rstd * gv.w + bv.w);
    __half2* op = (__half2*)(out + (size_t)m * C_ + tid * 4);
    op[0] = o01;
    op[1] = o23;
}

// ---------------------------------------------------------------------------
// FP16 tensor-core GEMM (mma.m16n8k16, fp32 accum) — exact R13 configuration.
// CTA tile 128x128, 8 warps (2 x 4), warp tile 64x32. 5-stage cp.async ring,
// K=32 halves per stage. Smem rows: 80 B = 64 B data + 16 B pad.
// mode 0: plain  1: exact GELU  2: += res[m]  3: scatter map_row(m), += res
// half_out: 1 -> store __half, 0 -> store float.
// ---------------------------------------------------------------------------
#define BM 128
#define BN 128
#define BKH 32                   // K halves per stage
#define ROWB 80                  // bytes per smem row
#define A_BYTES (BM * ROWB)      // 10240
#define NSTAGE 5
#define STAGE_BYTES (2 * A_BYTES)           // 20480
#define SMEM_GEMM (NSTAGE * STAGE_BYTES)    // 102400

__device__ __forceinline__ void cpa16(uint32_t smem_dst, const void* gsrc) {
    asm volatile("cp.async.cg.shared.global [%0], [%1], 16;\n"
                 :: "r"(smem_dst), "l"(gsrc));
}

__device__ __forceinline__ void mma_f16(float c[4], uint32_t a0, uint32_t a1,
                                        uint32_t a2, uint32_t a3,
                                        uint32_t b0, uint32_t b1) {
    asm volatile(
        "mma.sync.aligned.m16n8k16.row.col.f32.f16.f16.f32 "
        "{%0,%1,%2,%3}, {%4,%5,%6,%7}, {%8,%9}, {%0,%1,%2,%3};"
        : "+f"(c[0]), "+f"(c[1]), "+f"(c[2]), "+f"(c[3])
        : "r"(a0), "r"(a1), "r"(a2), "r"(a3), "r"(b0), "r"(b1));
}

__device__ __forceinline__ void ldsm4(uint32_t* a, uint32_t addr) {
    asm volatile("ldmatrix.sync.aligned.m8n8.x4.shared.b16 {%0,%1,%2,%3}, [%4];"
                 : "=r"(a[0]), "=r"(a[1]), "=r"(a[2]), "=r"(a[3]) : "r"(addr));
}

__global__ __launch_bounds__(256) void tgemm_kernel(
    const __half* __restrict__ A, const __half* __restrict__ Bt,
    const float* __restrict__ bias, void* __restrict__ Cout,
    int M, int N, int K, int mode, const float* __restrict__ res, int half_out)
{
    extern __shared__ char sm[];

    const int cRow = blockIdx.y, cCol = blockIdx.x;
    const int tid  = threadIdx.x;
    const int wid  = tid >> 5;
    const int lane = tid & 31;
    const int wm   = wid >> 2;       // 0..1  -> 64 M-rows
    const int wn   = wid & 3;        // 0..3  -> 32 N-cols
    const int grp  = lane >> 2;      // 0..7
    const int tig  = lane & 3;       // 0..3

    // ldmatrix lane address components (A: m16xk16 x4; B: n16xk16 x4)
    const int lrowA = (lane & 7) + ((lane >> 3) & 1) * 8;
    const int lcbA  = (lane >> 4) * 16;           // k-half byte offset 0/16
    const int lrowB = (lane & 7) + (lane >> 4) * 8;
    const int lcbB  = ((lane >> 3) & 1) * 16;

    const __half* Ab = A  + (size_t)cRow * BM * K;
    const __half* Bb = Bt + (size_t)cCol * BN * K;

    uint32_t smem_base = (uint32_t)__cvta_generic_to_shared(sm);
    const uint32_t aofs = (uint32_t)((wm * 64 + lrowA) * ROWB + lcbA);
    const uint32_t bofs = (uint32_t)A_BYTES +
                          (uint32_t)((wn * 32 + lrowB) * ROWB + lcbB);

    float c[4][4][4] = {};

    // Per stage: 128 rows x 64B data per tile; 4 chunks/row; 512 chunks = 256thr x 2.
    auto load_tile = [&](int t, int s) {
        const int k0 = t * BKH;
        uint32_t abase = smem_base + (uint32_t)(s * STAGE_BYTES);
        uint32_t bbase = abase + A_BYTES;
        #pragma unroll
        for (int cc = 0; cc < 2; cc++) {
            int id = tid * 2 + cc;
            int r = id >> 2, kc = id & 3;   // kc: 16B chunk = 8 halves
            cpa16(abase + (uint32_t)(r * ROWB + kc * 16),
                  Ab + (size_t)r * K + k0 + kc * 8);
            cpa16(bbase + (uint32_t)(r * ROWB + kc * 16),
                  Bb + (size_t)r * K + k0 + kc * 8);
        }
    };

    const int T = K / BKH;
    #pragma unroll
    for (int s = 0; s < NSTAGE - 1; s++) {
        load_tile(s, s);
        asm volatile("cp.async.commit_group;");
    }

    int ci = 0;
    int pi = NSTAGE - 1;
    for (int i = 0; i < T; i++) {
        asm volatile("cp.async.wait_group %0;" :: "n"(NSTAGE - 2));
        __syncthreads();

        if (i + NSTAGE - 1 < T) load_tile(i + NSTAGE - 1, pi);
        asm volatile("cp.async.commit_group;");

        const uint32_t stage = smem_base + (uint32_t)(ci * STAGE_BYTES);
        const uint32_t aStage = stage + aofs;
        const uint32_t bStage = stage + bofs;

        #pragma unroll
        for (int ks = 0; ks < 2; ks++) {          // two k16 steps per stage
            uint32_t a[4][4], b[4][2];
            #pragma unroll
            for (int mi = 0; mi < 4; mi++)
                ldsm4(a[mi], aStage + (uint32_t)(mi * 16 * ROWB + ks * 32));
            #pragma unroll
            for (int p = 0; p < 2; p++) {
                uint32_t t4[4];
                ldsm4(t4, bStage + (uint32_t)(p * 16 * ROWB + ks * 32));
                b[p*2    ][0] = t4[0];
                b[p*2    ][1] = t4[1];
                b[p*2 + 1][0] = t4[2];
                b[p*2 + 1][1] = t4[3];
            }
            #pragma unroll
            for (int mi = 0; mi < 4; mi++)
                #pragma unroll
                for (int ni = 0; ni < 4; ni++)
                    mma_f16(c[mi][ni], a[mi][0], a[mi][1], a[mi][2], a[mi][3],
                            b[ni][0], b[ni][1]);
        }
        ci = (ci + 1 == NSTAGE) ? 0 : ci + 1;
        pi = (pi + 1 == NSTAGE) ? 0 : pi + 1;
    }

    // epilogue (fp32 math)
    #pragma unroll
    for (int mi = 0; mi < 4; mi++) {
        #pragma unroll
        for (int rr = 0; rr < 2; rr++) {
            int m = cRow * BM + wm * 64 + mi * 16 + grp + rr * 8;
            int outm = (mode == 3) ? map_row(m) : m;
            #pragma unroll
            for (int ni = 0; ni < 4; ni++) {
                int n = cCol * BN + wn * 32 + ni * 8 + tig * 2;
                float v0 = c[mi][ni][rr * 2 + 0] + bias[n];
                float v1 = c[mi][ni][rr * 2 + 1] + bias[n + 1];
                if (mode == 1) {
                    v0 = 0.5f * v0 * (1.0f + erff(v0 * 0.70710678118654752f));
                    v1 = 0.5f * v1 * (1.0f + erff(v1 * 0.70710678118654752f));
                } else if (mode == 2) {
                    v0 += res[(size_t)m * N + n];
                    v1 += res[(size_t)m * N + n + 1];
                } else if (mode == 3) {
                    v0 += res[(size_t)outm * N + n];
                    v1 += res[(size_t)outm * N + n + 1];
                }
                if (half_out) {
                    *(__half2*)((__half*)Cout + (size_t)outm * N + n) =
                        __floats2half2_rn(v0, v1);
                } else {
                    float* Cp = (float*)Cout + (size_t)outm * N + n;
                    Cp[0] = v0;
                    Cp[1] = v1;
                }
            }
        }
    }
}

// ---------------------------------------------------------------------------
// Windowed attention on fp16 tensor cores (mma.m16n8k16, fp32 accum).
// One block (128 thr = 4 warps) per (window, head). Warp w owns S rows
// [16w, 16w+16). q/k stay fp16 (no conversion from the QKV GEMM output).
// q/k tiles: half[64][40] (80 B rows, proven conflict-free pattern).
// probs (fp16 A for PV) and V^T (fp16 B): half[.][72] (144 B rows, proven).
// Softmax in fp32 on sc[64][60].
// ---------------------------------------------------------------------------
#define QKH_STR 40   // halves per q/k row (80 B)
#define SCH_STR 72   // halves per probs/V^T row (144 B)
#define SC_STRF 60   // fp32 score row stride

__global__ __launch_bounds__(128) void attn_kernel(
    const __half* __restrict__ qkv, const float* __restrict__ rel_table,
    const int* __restrict__ rel_index, __half* __restrict__ ctx)
{
    __shared__ __half qs[64 * QKH_STR];
    __shared__ __half karr[64 * QKH_STR];
    __shared__ __half vsT[32 * SCH_STR];
    __shared__ __half scH[64 * SCH_STR];
    __shared__ float  sc[64 * SC_STRF];
    __shared__ int    grp[W2_];

    int blk  = blockIdx.x;
    int head = blk & (HEADS_ - 1);
    int win  = blk >> 4;
    int w    = win & (NW_ - 1);
    int tid  = threadIdx.x;
    int wid  = tid >> 5;
    int lane = tid & 31;

    // Zero fp16 tiles (pad rows/cols must contribute 0 to mma)
    {
        uint4 z = make_uint4(0, 0, 0, 0);
        for (int i = tid; i < (64 * QKH_STR) / 8; i += 128) {
            ((uint4*)qs)[i] = z;
            ((uint4*)karr)[i] = z;
        }
        for (int i = tid; i < (32 * SCH_STR) / 8; i += 128) ((uint4*)vsT)[i] = z;
        for (int i = tid; i < (64 * SCH_STR) / 8; i += 128) ((uint4*)scH)[i] = z;
    }
    __syncthreads();

    const size_t qbase = (size_t)win * W2_ * C3 + head * HD_;
    // q/k: direct 16B copies (both gmem and smem 16B-aligned)
    for (int idx = tid; idx < W2_ * 4; idx += 128) {
        int t = idx >> 2, dc = idx & 3;
        const uint4* p = (const uint4*)(qkv + qbase + (size_t)t * C3);
        ((uint4*)(qs   + t * QKH_STR))[dc] = p[dc];
        ((uint4*)(karr + t * QKH_STR))[dc] = p[dc + C_ / 8];
    }
    // v: transpose to [d][token] fp16
    for (int idx = tid; idx < W2_ * 16; idx += 128) {
        int t = idx >> 4, dp = idx & 15;
        __half2 vv = *(const __half2*)(qkv + qbase + (size_t)t * C3 + 2 * C_ + dp * 2);
        vsT[(dp * 2    ) * SCH_STR + t] = __low2half(vv);
        vsT[(dp * 2 + 1) * SCH_STR + t] = __high2half(vv);
    }
    if (tid < W2_) {
        int wh = w >> 2, ww = w & 3;
        int r = wh * WS_ + tid / WS_;
        int c = ww * WS_ + tid % WS_;
        int br = (r < HDIM - WS_) ? 0 : ((r < HDIM - SHIFT_) ? 1 : 2);
        int bc = (c < WDIM - WS_) ? 0 : ((c < WDIM - SHIFT_) ? 1 : 2);
        grp[tid] = br * 3 + bc;
    }
    __syncthreads();

    const float scale = 0.17677669529663687f; // 1/sqrt(32)
    const int m0 = wid * 16;
    const int lrowA = (lane & 7) + ((lane >> 3) & 1) * 8;
    const int lcbA  = (lane >> 4) * 16;
    const int lrowB = (lane & 7) + (lane >> 4) * 8;
    const int lcbB  = ((lane >> 3) & 1) * 16;
    const int rgrp  = lane >> 2;
    const int tig   = lane & 3;

    // ---- Scores: S[16 x 56] per warp = Q[16 x 32] @ K^T, k16 x 2 steps ----
    {
        uint32_t qb = (uint32_t)__cvta_generic_to_shared(qs) +
                      (uint32_t)((m0 + lrowA) * (QKH_STR * 2) + lcbA);
        uint32_t kb = (uint32_t)__cvta_generic_to_shared(karr) +
                      (uint32_t)(lrowB * (QKH_STR * 2) + lcbB);

        float c[7][4] = {};
        #pragma unroll
        for (int ks = 0; ks < 2; ks++) {
            uint32_t a[4];
            ldsm4(a, qb + ks * 32);
            uint32_t b[8][2];
            #pragma unroll
            for (int p = 0; p < 4; p++) {
                uint32_t t4[4];
                ldsm4(t4, kb + (uint32_t)(p * 16 * QKH_STR * 2) + ks * 32);
                b[p*2    ][0] = t4[0]; b[p*2    ][1] = t4[1];
                b[p*2 + 1][0] = t4[2]; b[p*2 + 1][1] = t4[3];
            }
            #pragma unroll
            for (int ni = 0; ni < 7; ni++)
                mma_f16(c[ni], a[0], a[1], a[2], a[3], b[ni][0], b[ni][1]);
        }

        // epilogue: scale + rel-pos bias + shift mask -> fp32 sc
        #pragma unroll
        for (int ni = 0; ni < 7; ni++) {
            #pragma unroll
            for (int h = 0; h < 2; h++) {
                int i = m0 + rgrp + h * 8;
                if (i < W2_) {
                    #pragma unroll
                    for (int e = 0; e < 2; e++) {
                        int j = ni * 8 + tig * 2 + e;
                        if (j < W2_) {
                            float bias = rel_table[rel_index[i * W2_ + j] * HEADS_ + head];
                            float mask = (grp[i] != grp[j]) ? -100.0f : 0.0f;
                            sc[i * SC_STRF + j] = c[ni][h * 2 + e] * scale + bias + mask;
                        }
                    }
                }
            }
        }
    }
    __syncthreads();

    // ---- Softmax per row (fp32), write fp16 probs into zero-padded scH ----
    if (tid < W2_) {
        float mx = -1e30f;
        #pragma unroll 7
        for (int j = 0; j < W2_; j++) mx = fmaxf(mx, sc[tid * SC_STRF + j]);
        float sum = 0.0f;
        #pragma unroll 7
        for (int j = 0; j < W2_; j++) {
            float e = __expf(sc[tid * SC_STRF + j] - mx);
            sc[tid * SC_STRF + j] = e;
            sum += e;
        }
        float inv = 1.0f / sum;
        #pragma unroll 7
        for (int j = 0; j < W2_; j++)
            scH[tid * SCH_STR + j] = __float2half(sc[tid * SC_STRF + j] * inv);
    }
    __syncthreads();

    // ---- PV: O[16 x 32] per warp = P[16 x 64pad] @ V[64pad x 32], k16 x 4 ----
    {
        uint32_t pb = (uint32_t)__cvta_generic_to_shared(scH) +
                      (uint32_t)((m0 + lrowA) * (SCH_STR * 2) + lcbA);
        uint32_t vb = (uint32_t)__cvta_generic_to_shared(vsT) +
                      (uint32_t)(lrowB * (SCH_STR * 2) + lcbB);

        float o[4][4] = {};
        #pragma unroll
        for (int ks = 0; ks < 4; ks++) {
            uint32_t a[4];
            ldsm4(a, pb + ks * 32);
            uint32_t b[4][2];
            #pragma unroll
            for (int p = 0; p < 2; p++) {
                uint32_t t4[4];
                ldsm4(t4, vb + (uint32_t)(p * 16 * SCH_STR * 2) + ks * 32);
                b[p*2    ][0] = t4[0]; b[p*2    ][1] = t4[1];
                b[p*2 + 1][0] = t4[2]; b[p*2 + 1][1] = t4[3];
            }
            #pragma unroll
            for (int ni = 0; ni < 4; ni++)
                mma_f16(o[ni], a[0], a[1], a[2], a[3], b[ni][0], b[ni][1]);
        }

        const size_t obase = (size_t)win * W2_ * C_ + head * HD_;
        #pragma unroll
        for (int ni = 0; ni < 4; ni++) {
            #pragma unroll
            for (int h = 0; h < 2; h++) {
                int i = m0 + rgrp + h * 8;
                if (i < W2_) {
                    int d = ni * 8 + tig * 2;
                    *(__half2*)&ctx[obase + (size_t)i * C_ + d] =
                        __floats2half2_rn(o[ni][h * 2], o[ni][h * 2 + 1]);
                }
            }
        }
    }
}

extern "C" void kernel_launch(void* const* d_in, const int* in_sizes, int n_in,
                              void* d_out, int out_size)
{
    const float* x         = (const float*)d_in[0];
    const float* g1        = (const float*)d_in[1];
    const float* b1        = (const float*)d_in[2];
    const float* wq        = (const float*)d_in[3];
    const float* bq        = (const float*)d_in[4];
    const float* wk        = (const float*)d_in[5];
    const float* bk        = (const float*)d_in[6];
    const float* wv        = (const float*)d_in[7];
    const float* bv        = (const float*)d_in[8];
    const float* rel_table = (const float*)d_in[9];
    const float* wo        = (const float*)d_in[10];
    const float* bo        = (const float*)d_in[11];
    const float* g2        = (const float*)d_in[12];
    const float* b2        = (const float*)d_in[13];
    const float* wi        = (const float*)d_in[14];
    const float* bi        = (const float*)d_in[15];
    const float* w_out     = (const float*)d_in[16];
    const float* b_out     = (const float*)d_in[17];
    const int*   rel_index = (const int*)d_in[18];
    float* out = (float*)d_out;

    __half *p_win, *p_qkv, *p_ctx, *p_h2, *p_wT;
    float  *p_x1, *p_bcat;
    cudaGetSymbolAddress((void**)&p_win,  g_win);
    cudaGetSymbolAddress((void**)&p_qkv,  g_qkv);
    cudaGetSymbolAddress((void**)&p_ctx,  g_ctx);
    cudaGetSymbolAddress((void**)&p_h2,   g_h2);
    cudaGetSymbolAddress((void**)&p_x1,   g_x1);
    cudaGetSymbolAddress((void**)&p_bcat, g_bcat);
    cudaGetSymbolAddress((void**)&p_wT,   g_wT);

    cudaFuncSetAttribute(tgemm_kernel,
                         cudaFuncAttributeMaxDynamicSharedMemorySize, SMEM_GEMM);

    // 0. weight transposes -> fp16 [N][K] K-major (qkvT = wqT|wkT|wvT stacked)
    transpose_kernel<<<dim3(16, 16), 256>>>(wq,    p_wT + WT_QKV,           C_,   C_);
    transpose_kernel<<<dim3(16, 16), 256>>>(wk,    p_wT + WT_QKV + C_*C_,   C_,   C_);
    transpose_kernel<<<dim3(16, 16), 256>>>(wv,    p_wT + WT_QKV + 2*C_*C_, C_,   C_);
    transpose_kernel<<<dim3(16, 16), 256>>>(wo,    p_wT + WT_O,             C_,   C_);
    transpose_kernel<<<dim3(64, 16), 256>>>(wi,    p_wT + WT_I,             C_,   MLPD);
    transpose_kernel<<<dim3(16, 64), 256>>>(w_out, p_wT + WT_OUT,           MLPD, C_);
    bcat_kernel<<<(C_ + 255) / 256, 256>>>(bq, bk, bv, p_bcat);

    // 1. LN1 + cyclic shift + window partition (gather) -> fp16
    ln_kernel<<<MTOK, 128>>>(x, g1, b1, p_win, 1);

    // 2. fused QKV projection -> fp16 qkv [MTOK][1536]
    dim3 gQKV(C3 / BN, MTOK / BM);
    tgemm_kernel<<<gQKV, 256, SMEM_GEMM>>>(p_win, p_wT + WT_QKV, p_bcat, p_qkv,
                                           MTOK, C3, C_, 0, nullptr, 1);

    // 3. windowed attention (fp16 tensor-core scores + softmax + PV) -> fp16 ctx
    attn_kernel<<<NWIN * HEADS_, 128>>>(p_qkv, rel_table, rel_index, p_ctx);

    // 4. output projection + window reverse + un-shift scatter + residual(x) -> fp32 x1
    dim3 gC(C_ / BN, MTOK / BM);
    tgemm_kernel<<<gC, 256, SMEM_GEMM>>>(p_ctx, p_wT + WT_O, bo, p_x1,
                                         MTOK, C_, C_, 3, x, 0);

    // 5. LN2 -> fp16
    ln_kernel<<<MTOK, 128>>>(p_x1, g2, b2, p_h2, 0);

    // 6. MLP up-projection + exact GELU -> fp16 mid (reuses qkv buffer)
    dim3 gM(MLPD / BN, MTOK / BM);
    tgemm_kernel<<<gM, 256, SMEM_GEMM>>>(p_h2, p_wT + WT_I, bi, p_qkv,
                                         MTOK, MLPD, C_, 1, nullptr, 1);

    // 7. MLP down-projection + residual(x1) -> fp32 final output
    tgemm_kernel<<<gC, 256, SMEM_GEMM>>>(p_qkv, p_wT + WT_OUT, b_out, out,
                                         MTOK, C_, MLPD, 2, p_x1, 0);
}

// round 17
// speedup vs baseline: 1.1914x; 1.0867x over previous
#include <cuda_runtime.h>
#include <cuda_fp16.h>
#include <math.h>
#include <stdint.h>

// Problem constants
#define BATCH   64
#define HDIM    28
#define WDIM    28
#define C_      512
#define HEADS_  16
#define WS_     7
#define SHIFT_  3
#define MLPD    2048
#define HD_     32
#define W2_     49
#define NW_     16
#define HW_     784
#define MTOK    50176   // BATCH*HW
#define NWIN    1024    // BATCH*NW
#define C3      1536    // 3*C_ fused qkv width

// Scratch (device globals: no allocation allowed in kernel_launch)
__device__ __half g_win[MTOK * C_];
__device__ __half g_qkv[(size_t)MTOK * MLPD];  // fused qkv [MTOK][1536]; also mid
__device__ __half g_ctx[MTOK * C_];
__device__ __half g_h2[MTOK * C_];
__device__ float  g_x1[MTOK * C_];
__device__ float  g_bcat[C3];
// Transposed (K-major, [N][K]) fp16 weights: qkvT | woT | wiT | woutT
#define WT_QKV 0
#define WT_O   (C3 * C_)
#define WT_I   (WT_O + C_ * C_)
#define WT_OUT (WT_I + MLPD * C_)
__device__ __half g_wT[WT_OUT + C_ * MLPD];

// Map window-partition row m -> token row in the unshifted [B,H*W] layout.
__device__ __forceinline__ int map_row(int m) {
    int bb  = m / HW_;
    int rem = m - bb * HW_;
    int w   = rem / W2_;
    int t   = rem - w * W2_;
    int wh = w >> 2, ww = w & 3;
    int th = t / WS_, tw = t - th * WS_;
    int r = wh * WS_ + th + SHIFT_; if (r >= HDIM) r -= HDIM;
    int c = ww * WS_ + tw + SHIFT_; if (c >= WDIM) c -= WDIM;
    return bb * HW_ + r * WDIM + c;
}

// Tiled transpose + fp32->fp16: out[Cc][R] = half(in[R][Cc]^T).
__global__ __launch_bounds__(256) void transpose_kernel(
    const float* __restrict__ in, __half* __restrict__ out, int R, int Cc)
{
    __shared__ float t[32][33];
    int bx = blockIdx.x * 32, by = blockIdx.y * 32;
    int tx = threadIdx.x & 31, ty = threadIdx.x >> 5;
    #pragma unroll
    for (int j = 0; j < 32; j += 8)
        t[ty + j][tx] = in[(size_t)(by + ty + j) * Cc + bx + tx];
    __syncthreads();
    #pragma unroll
    for (int j = 0; j < 32; j += 8)
        out[(size_t)(bx + ty + j) * R + by + tx] = __float2half(t[tx][ty + j]);
}

// Concat qkv biases (fp32)
__global__ __launch_bounds__(256) void bcat_kernel(
    const float* __restrict__ bq, const float* __restrict__ bk,
    const float* __restrict__ bv, float* __restrict__ bcat)
{
    int idx = blockIdx.x * 256 + threadIdx.x;
    if (idx < C_) {
        bcat[idx        ] = bq[idx];
        bcat[idx + C_   ] = bk[idx];
        bcat[idx + 2*C_ ] = bv[idx];
    }
}

// LayerNorm over C=512, one block per token row; fp32 in, fp16 out.
__global__ __launch_bounds__(128) void ln_kernel(
    const float* __restrict__ in, const float* __restrict__ g,
    const float* __restrict__ b, __half* __restrict__ out, int gather)
{
    int m = blockIdx.x;
    int src = gather ? map_row(m) : m;
    int tid = threadIdx.x;

    float4 xv = ((const float4*)(in + (size_t)src * C_))[tid];
    float s  = xv.x + xv.y + xv.z + xv.w;
    float s2 = xv.x*xv.x + xv.y*xv.y + xv.z*xv.z + xv.w*xv.w;
    #pragma unroll
    for (int off = 16; off; off >>= 1) {
        s  += __shfl_xor_sync(0xffffffffu, s,  off);
        s2 += __shfl_xor_sync(0xffffffffu, s2, off);
    }
    __shared__ float red[8];
    int wid = tid >> 5;
    if ((tid & 31) == 0) { red[wid] = s; red[4 + wid] = s2; }
    __syncthreads();
    s  = red[0] + red[1] + red[2] + red[3];
    s2 = red[4] + red[5] + red[6] + red[7];
    float mu   = s * (1.0f / C_);
    float var  = fmaf(-mu, mu, s2 * (1.0f / C_));
    float rstd = rsqrtf(var + 1e-5f);

    float4 gv = ((const float4*)g)[tid];
    float4 bv = ((const float4*)b)[tid];
    __half2 o01 = __floats2half2_rn((xv.x - mu) * rstd * gv.x + bv.x,
                                    (xv.y - mu) * rstd * gv.y + bv.y);
    __half2 o23 = __floats2half2_rn((xv.z - mu) * rstd * gv.z + bv.z,
                                    (xv.w - mu) * rstd * gv.w + bv.w);
    __half2* op = (__half2*)(out + (size_t)m * C_ + tid * 4);
    op[0] = o01;
    op[1] = o23;
}

// ---------------------------------------------------------------------------
// FP16 tensor-core GEMM (mma.m16n8k16, fp32 accum).
// CTA tile 128x256, 512 threads = 16 warps (2 x 8), warp tile 64x32
// (fragment code identical to the proven R13 kernel). 6-stage cp.async ring,
// K=32 halves per stage, prefetch lead 5 stages.
// Smem rows: 80 B = 64 B data + 16 B pad (proven conflict-free).
// mode 0: plain  1: exact GELU  2: += res[m]  3: scatter map_row(m), += res
// half_out: 1 -> store __half, 0 -> store float.
// ---------------------------------------------------------------------------
#define BM 128
#define BN 256
#define GT 512
#define BKH 32                   // K halves per stage
#define ROWB 80                  // bytes per smem row
#define A_BYTES (BM * ROWB)      // 10240
#define B_BYTES (BN * ROWB)      // 20480
#define NSTAGE 6
#define STAGE_BYTES (A_BYTES + B_BYTES)     // 30720
#define SMEM_GEMM (NSTAGE * STAGE_BYTES)    // 184320

__device__ __forceinline__ void cpa16(uint32_t smem_dst, const void* gsrc) {
    asm volatile("cp.async.cg.shared.global [%0], [%1], 16;\n"
                 :: "r"(smem_dst), "l"(gsrc));
}

__device__ __forceinline__ void mma_f16(float c[4], uint32_t a0, uint32_t a1,
                                        uint32_t a2, uint32_t a3,
                                        uint32_t b0, uint32_t b1) {
    asm volatile(
        "mma.sync.aligned.m16n8k16.row.col.f32.f16.f16.f32 "
        "{%0,%1,%2,%3}, {%4,%5,%6,%7}, {%8,%9}, {%0,%1,%2,%3};"
        : "+f"(c[0]), "+f"(c[1]), "+f"(c[2]), "+f"(c[3])
        : "r"(a0), "r"(a1), "r"(a2), "r"(a3), "r"(b0), "r"(b1));
}

__device__ __forceinline__ void ldsm4(uint32_t* a, uint32_t addr) {
    asm volatile("ldmatrix.sync.aligned.m8n8.x4.shared.b16 {%0,%1,%2,%3}, [%4];"
                 : "=r"(a[0]), "=r"(a[1]), "=r"(a[2]), "=r"(a[3]) : "r"(addr));
}

__global__ __launch_bounds__(GT, 1) void tgemm_kernel(
    const __half* __restrict__ A, const __half* __restrict__ Bt,
    const float* __restrict__ bias, void* __restrict__ Cout,
    int M, int N, int K, int mode, const float* __restrict__ res, int half_out)
{
    extern __shared__ char sm[];

    const int cRow = blockIdx.y, cCol = blockIdx.x;
    const int tid  = threadIdx.x;
    const int wid  = tid >> 5;
    const int lane = tid & 31;
    const int wm   = wid >> 3;       // 0..1  -> 64 M-rows
    const int wn   = wid & 7;        // 0..7  -> 32 N-cols
    const int grp  = lane >> 2;      // 0..7
    const int tig  = lane & 3;       // 0..3

    // ldmatrix lane address components (A: m16xk16 x4; B: n16xk16 x4)
    const int lrowA = (lane & 7) + ((lane >> 3) & 1) * 8;
    const int lcbA  = (lane >> 4) * 16;           // k-half byte offset 0/16
    const int lrowB = (lane & 7) + (lane >> 4) * 8;
    const int lcbB  = ((lane >> 3) & 1) * 16;

    const __half* Ab = A  + (size_t)cRow * BM * K;
    const __half* Bb = Bt + (size_t)cCol * BN * K;

    uint32_t smem_base = (uint32_t)__cvta_generic_to_shared(sm);
    const uint32_t aofs = (uint32_t)((wm * 64 + lrowA) * ROWB + lcbA);
    const uint32_t bofs = (uint32_t)A_BYTES +
                          (uint32_t)((wn * 32 + lrowB) * ROWB + lcbB);

    float c[4][4][4] = {};

    // Per stage: A 512 chunks (1/thread), B 1024 chunks (2/thread).
    auto load_tile = [&](int t, int s) {
        const int k0 = t * BKH;
        uint32_t abase = smem_base + (uint32_t)(s * STAGE_BYTES);
        uint32_t bbase = abase + A_BYTES;
        {
            int r = tid >> 2, kc = tid & 3;   // kc: 16B chunk = 8 halves
            cpa16(abase + (uint32_t)(r * ROWB + kc * 16),
                  Ab + (size_t)r * K + k0 + kc * 8);
        }
        #pragma unroll
        for (int cc = 0; cc < 2; cc++) {
            int id = tid * 2 + cc;
            int r = id >> 2, kc = id & 3;
            cpa16(bbase + (uint32_t)(r * ROWB + kc * 16),
                  Bb + (size_t)r * K + k0 + kc * 8);
        }
    };

    const int T = K / BKH;
    #pragma unroll
    for (int s = 0; s < NSTAGE - 1; s++) {
        load_tile(s, s);
        asm volatile("cp.async.commit_group;");
    }

    int ci = 0;
    int pi = NSTAGE - 1;
    for (int i = 0; i < T; i++) {
        asm volatile("cp.async.wait_group %0;" :: "n"(NSTAGE - 2));
        __syncthreads();

        if (i + NSTAGE - 1 < T) load_tile(i + NSTAGE - 1, pi);
        asm volatile("cp.async.commit_group;");

        const uint32_t stage = smem_base + (uint32_t)(ci * STAGE_BYTES);
        const uint32_t aStage = stage + aofs;
        const uint32_t bStage = stage + bofs;

        #pragma unroll
        for (int ks = 0; ks < 2; ks++) {          // two k16 steps per stage
            uint32_t a[4][4], b[4][2];
            #pragma unroll
            for (int mi = 0; mi < 4; mi++)
                ldsm4(a[mi], aStage + (uint32_t)(mi * 16 * ROWB + ks * 32));
            #pragma unroll
            for (int p = 0; p < 2; p++) {
                uint32_t t4[4];
                ldsm4(t4, bStage + (uint32_t)(p * 16 * ROWB + ks * 32));
                b[p*2    ][0] = t4[0];
                b[p*2    ][1] = t4[1];
                b[p*2 + 1][0] = t4[2];
                b[p*2 + 1][1] = t4[3];
            }
            #pragma unroll
            for (int mi = 0; mi < 4; mi++)
                #pragma unroll
                for (int ni = 0; ni < 4; ni++)
                    mma_f16(c[mi][ni], a[mi][0], a[mi][1], a[mi][2], a[mi][3],
                            b[ni][0], b[ni][1]);
        }
        ci = (ci + 1 == NSTAGE) ? 0 : ci + 1;
        pi = (pi + 1 == NSTAGE) ? 0 : pi + 1;
    }

    // epilogue (fp32 math)
    #pragma unroll
    for (int mi = 0; mi < 4; mi++) {
        #pragma unroll
        for (int rr = 0; rr < 2; rr++) {
            int m = cRow * BM + wm * 64 + mi * 16 + grp + rr * 8;
            int outm = (mode == 3) ? map_row(m) : m;
            #pragma unroll
            for (int ni = 0; ni < 4; ni++) {
                int n = cCol * BN + wn * 32 + ni * 8 + tig * 2;
                float v0 = c[mi][ni][rr * 2 + 0] + bias[n];
                float v1 = c[mi][ni][rr * 2 + 1] + bias[n + 1];
                if (mode == 1) {
                    v0 = 0.5f * v0 * (1.0f + erff(v0 * 0.70710678118654752f));
                    v1 = 0.5f * v1 * (1.0f + erff(v1 * 0.70710678118654752f));
                } else if (mode == 2) {
                    v0 += res[(size_t)m * N + n];
                    v1 += res[(size_t)m * N + n + 1];
                } else if (mode == 3) {
                    v0 += res[(size_t)outm * N + n];
                    v1 += res[(size_t)outm * N + n + 1];
                }
                if (half_out) {
                    *(__half2*)((__half*)Cout + (size_t)outm * N + n) =
                        __floats2half2_rn(v0, v1);
                } else {
                    float* Cp = (float*)Cout + (size_t)outm * N + n;
                    Cp[0] = v0;
                    Cp[1] = v1;
                }
            }
        }
    }
}

// ---------------------------------------------------------------------------
// Windowed attention on fp16 tensor cores (mma.m16n8k16, fp32 accum).
// One block (128 thr = 4 warps) per (window, head).
// ---------------------------------------------------------------------------
#define QKH_STR 40   // halves per q/k row (80 B)
#define SCH_STR 72   // halves per probs/V^T row (144 B)
#define SC_STRF 60   // fp32 score row stride

__global__ __launch_bounds__(128) void attn_kernel(
    const __half* __restrict__ qkv, const float* __restrict__ rel_table,
    const int* __restrict__ rel_index, __half* __restrict__ ctx)
{
    __shared__ __half qs[64 * QKH_STR];
    __shared__ __half karr[64 * QKH_STR];
    __shared__ __half vsT[32 * SCH_STR];
    __shared__ __half scH[64 * SCH_STR];
    __shared__ float  sc[64 * SC_STRF];
    __shared__ int    grp[W2_];

    int blk  = blockIdx.x;
    int head = blk & (HEADS_ - 1);
    int win  = blk >> 4;
    int w    = win & (NW_ - 1);
    int tid  = threadIdx.x;
    int wid  = tid >> 5;
    int lane = tid & 31;

    // Zero fp16 tiles (pad rows/cols must contribute 0 to mma)
    {
        uint4 z = make_uint4(0, 0, 0, 0);
        for (int i = tid; i < (64 * QKH_STR) / 8; i += 128) {
            ((uint4*)qs)[i] = z;
            ((uint4*)karr)[i] = z;
        }
        for (int i = tid; i < (32 * SCH_STR) / 8; i += 128) ((uint4*)vsT)[i] = z;
        for (int i = tid; i < (64 * SCH_STR) / 8; i += 128) ((uint4*)scH)[i] = z;
    }
    __syncthreads();

    const size_t qbase = (size_t)win * W2_ * C3 + head * HD_;
    // q/k: direct 16B copies (both gmem and smem 16B-aligned)
    for (int idx = tid; idx < W2_ * 4; idx += 128) {
        int t = idx >> 2, dc = idx & 3;
        const uint4* p = (const uint4*)(qkv + qbase + (size_t)t * C3);
        ((uint4*)(qs   + t * QKH_STR))[dc] = p[dc];
        ((uint4*)(karr + t * QKH_STR))[dc] = p[dc + C_ / 8];
    }
    // v: transpose to [d][token] fp16
    for (int idx = tid; idx < W2_ * 16; idx += 128) {
        int t = idx >> 4, dp = idx & 15;
        __half2 vv = *(const __half2*)(qkv + qbase + (size_t)t * C3 + 2 * C_ + dp * 2);
        vsT[(dp * 2    ) * SCH_STR + t] = __low2half(vv);
        vsT[(dp * 2 + 1) * SCH_STR + t] = __high2half(vv);
    }
    if (tid < W2_) {
        int wh = w >> 2, ww = w & 3;
        int r = wh * WS_ + tid / WS_;
        int c = ww * WS_ + tid % WS_;
        int br = (r < HDIM - WS_) ? 0 : ((r < HDIM - SHIFT_) ? 1 : 2);
        int bc = (c < WDIM - WS_) ? 0 : ((c < WDIM - SHIFT_) ? 1 : 2);
        grp[tid] = br * 3 + bc;
    }
    __syncthreads();

    const float scale = 0.17677669529663687f; // 1/sqrt(32)
    const int m0 = wid * 16;
    const int lrowA = (lane & 7) + ((lane >> 3) & 1) * 8;
    const int lcbA  = (lane >> 4) * 16;
    const int lrowB = (lane & 7) + (lane >> 4) * 8;
    const int lcbB  = ((lane >> 3) & 1) * 16;
    const int rgrp  = lane >> 2;
    const int tig   = lane & 3;

    // ---- Scores: S[16 x 56] per warp = Q[16 x 32] @ K^T, k16 x 2 steps ----
    {
        uint32_t qb = (uint32_t)__cvta_generic_to_shared(qs) +
                      (uint32_t)((m0 + lrowA) * (QKH_STR * 2) + lcbA);
        uint32_t kb = (uint32_t)__cvta_generic_to_shared(karr) +
                      (uint32_t)(lrowB * (QKH_STR * 2) + lcbB);

        float c[7][4] = {};
        #pragma unroll
        for (int ks = 0; ks < 2; ks++) {
            uint32_t a[4];
            ldsm4(a, qb + ks * 32);
            uint32_t b[8][2];
            #pragma unroll
            for (int p = 0; p < 4; p++) {
                uint32_t t4[4];
                ldsm4(t4, kb + (uint32_t)(p * 16 * QKH_STR * 2) + ks * 32);
                b[p*2    ][0] = t4[0]; b[p*2    ][1] = t4[1];
                b[p*2 + 1][0] = t4[2]; b[p*2 + 1][1] = t4[3];
            }
            #pragma unroll
            for (int ni = 0; ni < 7; ni++)
                mma_f16(c[ni], a[0], a[1], a[2], a[3], b[ni][0], b[ni][1]);
        }

        // epilogue: scale + rel-pos bias + shift mask -> fp32 sc
        #pragma unroll
        for (int ni = 0; ni < 7; ni++) {
            #pragma unroll
            for (int h = 0; h < 2; h++) {
                int i = m0 + rgrp + h * 8;
                if (i < W2_) {
                    #pragma unroll
                    for (int e = 0; e < 2; e++) {
                        int j = ni * 8 + tig * 2 + e;
                        if (j < W2_) {
                            float bias = rel_table[rel_index[i * W2_ + j] * HEADS_ + head];
                            float mask = (grp[i] != grp[j]) ? -100.0f : 0.0f;
                            sc[i * SC_STRF + j] = c[ni][h * 2 + e] * scale + bias + mask;
                        }
                    }
                }
            }
        }
    }
    __syncthreads();

    // ---- Softmax per row (fp32), write fp16 probs into zero-padded scH ----
    if (tid < W2_) {
        float mx = -1e30f;
        #pragma unroll 7
        for (int j = 0; j < W2_; j++) mx = fmaxf(mx, sc[tid * SC_STRF + j]);
        float sum = 0.0f;
        #pragma unroll 7
        for (int j = 0; j < W2_; j++) {
            float e = __expf(sc[tid * SC_STRF + j] - mx);
            sc[tid * SC_STRF + j] = e;
            sum += e;
        }
        float inv = 1.0f / sum;
        #pragma unroll 7
        for (int j = 0; j < W2_; j++)
            scH[tid * SCH_STR + j] = __float2half(sc[tid * SC_STRF + j] * inv);
    }
    __syncthreads();

    // ---- PV: O[16 x 32] per warp = P[16 x 64pad] @ V[64pad x 32], k16 x 4 ----
    {
        uint32_t pb = (uint32_t)__cvta_generic_to_shared(scH) +
                      (uint32_t)((m0 + lrowA) * (SCH_STR * 2) + lcbA);
        uint32_t vb = (uint32_t)__cvta_generic_to_shared(vsT) +
                      (uint32_t)(lrowB * (SCH_STR * 2) + lcbB);

        float o[4][4] = {};
        #pragma unroll
        for (int ks = 0; ks < 4; ks++) {
            uint32_t a[4];
            ldsm4(a, pb + ks * 32);
            uint32_t b[4][2];
            #pragma unroll
            for (int p = 0; p < 2; p++) {
                uint32_t t4[4];
                ldsm4(t4, vb + (uint32_t)(p * 16 * SCH_STR * 2) + ks * 32);
                b[p*2    ][0] = t4[0]; b[p*2    ][1] = t4[1];
                b[p*2 + 1][0] = t4[2]; b[p*2 + 1][1] = t4[3];
            }
            #pragma unroll
            for (int ni = 0; ni < 4; ni++)
                mma_f16(o[ni], a[0], a[1], a[2], a[3], b[ni][0], b[ni][1]);
        }

        const size_t obase = (size_t)win * W2_ * C_ + head * HD_;
        #pragma unroll
        for (int ni = 0; ni < 4; ni++) {
            #pragma unroll
            for (int h = 0; h < 2; h++) {
                int i = m0 + rgrp + h * 8;
                if (i < W2_) {
                    int d = ni * 8 + tig * 2;
                    *(__half2*)&ctx[obase + (size_t)i * C_ + d] =
                        __floats2half2_rn(o[ni][h * 2], o[ni][h * 2 + 1]);
                }
            }
        }
    }
}

extern "C" void kernel_launch(void* const* d_in, const int* in_sizes, int n_in,
                              void* d_out, int out_size)
{
    const float* x         = (const float*)d_in[0];
    const float* g1        = (const float*)d_in[1];
    const float* b1        = (const float*)d_in[2];
    const float* wq        = (const float*)d_in[3];
    const float* bq        = (const float*)d_in[4];
    const float* wk        = (const float*)d_in[5];
    const float* bk        = (const float*)d_in[6];
    const float* wv        = (const float*)d_in[7];
    const float* bv        = (const float*)d_in[8];
    const float* rel_table = (const float*)d_in[9];
    const float* wo        = (const float*)d_in[10];
    const float* bo        = (const float*)d_in[11];
    const float* g2        = (const float*)d_in[12];
    const float* b2        = (const float*)d_in[13];
    const float* wi        = (const float*)d_in[14];
    const float* bi        = (const float*)d_in[15];
    const float* w_out     = (const float*)d_in[16];
    const float* b_out     = (const float*)d_in[17];
    const int*   rel_index = (const int*)d_in[18];
    float* out = (float*)d_out;

    __half *p_win, *p_qkv, *p_ctx, *p_h2, *p_wT;
    float  *p_x1, *p_bcat;
    cudaGetSymbolAddress((void**)&p_win,  g_win);
    cudaGetSymbolAddress((void**)&p_qkv,  g_qkv);
    cudaGetSymbolAddress((void**)&p_ctx,  g_ctx);
    cudaGetSymbolAddress((void**)&p_h2,   g_h2);
    cudaGetSymbolAddress((void**)&p_x1,   g_x1);
    cudaGetSymbolAddress((void**)&p_bcat, g_bcat);
    cudaGetSymbolAddress((void**)&p_wT,   g_wT);

    cudaFuncSetAttribute(tgemm_kernel,
                         cudaFuncAttributeMaxDynamicSharedMemorySize, SMEM_GEMM);

    // 0. weight transposes -> fp16 [N][K] K-major (qkvT = wqT|wkT|wvT stacked)
    transpose_kernel<<<dim3(16, 16), 256>>>(wq,    p_wT + WT_QKV,           C_,   C_);
    transpose_kernel<<<dim3(16, 16), 256>>>(wk,    p_wT + WT_QKV + C_*C_,   C_,   C_);
    transpose_kernel<<<dim3(16, 16), 256>>>(wv,    p_wT + WT_QKV + 2*C_*C_, C_,   C_);
    transpose_kernel<<<dim3(16, 16), 256>>>(wo,    p_wT + WT_O,             C_,   C_);
    transpose_kernel<<<dim3(64, 16), 256>>>(wi,    p_wT + WT_I,             C_,   MLPD);
    transpose_kernel<<<dim3(16, 64), 256>>>(w_out, p_wT + WT_OUT,           MLPD, C_);
    bcat_kernel<<<(C_ + 255) / 256, 256>>>(bq, bk, bv, p_bcat);

    // 1. LN1 + cyclic shift + window partition (gather) -> fp16
    ln_kernel<<<MTOK, 128>>>(x, g1, b1, p_win, 1);

    // 2. fused QKV projection -> fp16 qkv [MTOK][1536]
    dim3 gQKV(C3 / BN, MTOK / BM);
    tgemm_kernel<<<gQKV, GT, SMEM_GEMM>>>(p_win, p_wT + WT_QKV, p_bcat, p_qkv,
                                          MTOK, C3, C_, 0, nullptr, 1);

    // 3. windowed attention (fp16 tensor-core scores + softmax + PV) -> fp16 ctx
    attn_kernel<<<NWIN * HEADS_, 128>>>(p_qkv, rel_table, rel_index, p_ctx);

    // 4. output projection + window reverse + un-shift scatter + residual(x) -> fp32 x1
    dim3 gC(C_ / BN, MTOK / BM);
    tgemm_kernel<<<gC, GT, SMEM_GEMM>>>(p_ctx, p_wT + WT_O, bo, p_x1,
                                        MTOK, C_, C_, 3, x, 0);

    // 5. LN2 -> fp16
    ln_kernel<<<MTOK, 128>>>(p_x1, g2, b2, p_h2, 0);

    // 6. MLP up-projection + exact GELU -> fp16 mid (reuses qkv buffer)
    dim3 gM(MLPD / BN, MTOK / BM);
    tgemm_kernel<<<gM, GT, SMEM_GEMM>>>(p_h2, p_wT + WT_I, bi, p_qkv,
                                        MTOK, MLPD, C_, 1, nullptr, 1);

    // 7. MLP down-projection + residual(x1) -> fp32 final output
    tgemm_kernel<<<gC, GT, SMEM_GEMM>>>(p_qkv, p_wT + WT_OUT, b_out, out,
                                        MTOK, C_, MLPD, 2, p_x1, 0);
}